// round 2
// baseline (speedup 1.0000x reference)
#include <cuda_runtime.h>

#define BINS 10
#define TPB  256

// Global scratch (allocation-free: __device__ globals).
__device__ double g_cnt[BINS];
__device__ double g_sum[BINS];

__global__ void ghm_init()
{
    if (threadIdx.x < BINS) {
        g_cnt[threadIdx.x] = 0.0;
        g_sum[threadIdx.x] = 0.0;
    }
}

// One element: logit x, one-hot label y (0.0f or 1.0f).
// g   = |sigmoid(x) - y|
// bce = max(x,0) - x*y + log1p(exp(-|x|))
// Shares e = exp(-|x|):
//   sigmoid(x) = (x>=0) ? 1/(1+e) : e/(1+e)
//   g numerator = ((y!=0) == (x>=0)) ? e : 1;  g = num/(1+e)
__device__ __forceinline__ void ghm_elem(float x, float y, float2 (*hist)[TPB], int tid)
{
    float ax = fabsf(x);
    float e  = __expf(-ax);                 // MUFU.EX2 (+scale)
    float d  = 1.0f + e;
    bool xpos = (x >= 0.0f);
    bool yone = (y != 0.0f);
    float num = (xpos == yone) ? e : 1.0f;
    float g   = __fdividef(num, d);         // MUFU.RCP + FMUL
    int bin = (int)(g * 9.9999f);           // g in [0,1] -> [0,9]
    bin = max(0, min(bin, BINS - 1));
    float bce = fmaxf(x, 0.0f) - x * y + __logf(d);  // MUFU.LG2 (+scale)
    float2 h = hist[bin][tid];
    h.x += 1.0f;
    h.y += bce;
    hist[bin][tid] = h;
}

__global__ void __launch_bounds__(TPB) ghm_hist(const float4* __restrict__ x4,
                                                const int4*   __restrict__ t4,
                                                int nquads)
{
    // Privatized histogram: hist[bin][tid] as (count, bce_sum).
    // Address = bin*2048 + tid*8 -> bank = tid (mod 32): conflict-free for any bin mix.
    __shared__ float2 hist[BINS][TPB];
    const int tid = threadIdx.x;
#pragma unroll
    for (int b = 0; b < BINS; b++) hist[b][tid] = make_float2(0.0f, 0.0f);
    __syncthreads();

    const int stride = gridDim.x * TPB;
    for (int i = blockIdx.x * TPB + tid; i < nquads; i += stride) {
        // 4 rows per iteration: rows 4i..4i+3, each with 2 logits.
        float4 xa = x4[2 * i];       // rows 4i, 4i+1
        float4 xb = x4[2 * i + 1];   // rows 4i+2, 4i+3
        int4   tv = t4[i];           // int32 targets (values 0 or 1)

        ghm_elem(xa.x, (tv.x == 0) ? 1.0f : 0.0f, hist, tid);
        ghm_elem(xa.y, (tv.x == 1) ? 1.0f : 0.0f, hist, tid);
        ghm_elem(xa.z, (tv.y == 0) ? 1.0f : 0.0f, hist, tid);
        ghm_elem(xa.w, (tv.y == 1) ? 1.0f : 0.0f, hist, tid);
        ghm_elem(xb.x, (tv.z == 0) ? 1.0f : 0.0f, hist, tid);
        ghm_elem(xb.y, (tv.z == 1) ? 1.0f : 0.0f, hist, tid);
        ghm_elem(xb.z, (tv.w == 0) ? 1.0f : 0.0f, hist, tid);
        ghm_elem(xb.w, (tv.w == 1) ? 1.0f : 0.0f, hist, tid);
    }
    __syncthreads();

    // Tree-reduce the 256 per-thread columns for all 10 bins.
    for (int off = TPB / 2; off > 0; off >>= 1) {
        if (tid < off) {
#pragma unroll
            for (int b = 0; b < BINS; b++) {
                float2 a = hist[b][tid];
                float2 c = hist[b][tid + off];
                hist[b][tid] = make_float2(a.x + c.x, a.y + c.y);
            }
        }
        __syncthreads();
    }

    if (tid < BINS) {
        atomicAdd(&g_cnt[tid], (double)hist[tid][0].x);
        atomicAdd(&g_sum[tid], (double)hist[tid][0].y);
    }
}

__global__ void ghm_final(float* __restrict__ out)
{
    if (threadIdx.x == 0) {
        double nonempty = 0.0;
        for (int b = 0; b < BINS; b++) nonempty += (g_cnt[b] > 0.0) ? 1.0 : 0.0;
        // mean(weight*bce) = (1/N) * sum_b (N/gd_b) * sum_bce_b = sum_b sum_bce_b / gd_b
        double loss = 0.0;
        for (int b = 0; b < BINS; b++) {
            double gd = g_cnt[b] * nonempty;
            if (gd < 1e-4) gd = 1e-4;
            loss += g_sum[b] / gd;
        }
        out[0] = (float)loss;
    }
}

extern "C" void kernel_launch(void* const* d_in, const int* in_sizes, int n_in,
                              void* d_out, int out_size)
{
    // x: [B,2] float32 (2B elements), target: [B] int32 (B elements).
    // Identify by element count (x has 2x the elements of target).
    const float* x;
    const int*   t;
    int nrows;
    if (in_sizes[0] >= 2 * in_sizes[1]) {
        x = (const float*)d_in[0];
        t = (const int*)d_in[1];
        nrows = in_sizes[1];
    } else {
        x = (const float*)d_in[1];
        t = (const int*)d_in[0];
        nrows = in_sizes[0];
    }
    int nquads = nrows >> 2;  // 4 rows (8 logits) per loop iteration

    ghm_init<<<1, 32>>>();
    const int blocks = 1216;  // 152 SMs * 8 blocks (20KB smem, 256 thr each)
    ghm_hist<<<blocks, TPB>>>((const float4*)x, (const int4*)t, nquads);
    ghm_final<<<1, 32>>>((float*)d_out);
}